// round 17
// baseline (speedup 1.0000x reference)
#include <cuda_runtime.h>
#include <cuda_fp16.h>
#include <math.h>

#define B_    2
#define T_    2048
#define E_    2048
#define H_    32
#define G_    8
#define D_    64
#define QKV_F 3072
#define QPK_  4

typedef unsigned int u32;

// ---------------- scratch (device globals; no allocation allowed) ----------
__device__ __half g_qkv16[(size_t)B_ * T_ * QKV_F];
__device__ __half g_xh [(size_t)B_ * T_ * E_];
__device__ __half g_awh[(size_t)QKV_F * E_];
__device__ __half g_pwh[(size_t)E_ * E_];
__device__ __half g_qh [(size_t)B_ * H_ * T_ * D_];
__device__ __half g_kh [(size_t)B_ * G_ * T_ * D_];
__device__ __half g_vh [(size_t)B_ * G_ * T_ * D_];
__device__ __half g_ath[(size_t)B_ * T_ * E_];

// ---------------- helpers --------------------------------------------------
__device__ __forceinline__ u32 packh(float lo, float hi) {
    u32 r;
    asm("cvt.rn.f16x2.f32 %0, %1, %2;" : "=r"(r) : "f"(hi), "f"(lo));
    return r;
}

__device__ __forceinline__ void mma16816(float* c, u32 a0, u32 a1, u32 a2, u32 a3,
                                         u32 b0, u32 b1) {
    asm volatile(
        "mma.sync.aligned.m16n8k16.row.col.f32.f16.f16.f32 "
        "{%0,%1,%2,%3}, {%4,%5,%6,%7}, {%8,%9}, {%0,%1,%2,%3};"
        : "+f"(c[0]), "+f"(c[1]), "+f"(c[2]), "+f"(c[3])
        : "r"(a0), "r"(a1), "r"(a2), "r"(a3), "r"(b0), "r"(b1));
}

__device__ __forceinline__ void ldsm4(u32* r, u32 a) {
    asm volatile("ldmatrix.sync.aligned.m8n8.x4.shared.b16 {%0,%1,%2,%3}, [%4];"
                 : "=r"(r[0]), "=r"(r[1]), "=r"(r[2]), "=r"(r[3]) : "r"(a));
}
__device__ __forceinline__ void ldsm4t(u32* r, const __half* p) {
    u32 a = (u32)__cvta_generic_to_shared(p);
    asm volatile("ldmatrix.sync.aligned.m8n8.x4.trans.shared.b16 {%0,%1,%2,%3}, [%4];"
                 : "=r"(r[0]), "=r"(r[1]), "=r"(r[2]), "=r"(r[3]) : "r"(a));
}

__device__ __forceinline__ u32 smem_u32(const void* p) {
    return (u32)__cvta_generic_to_shared(p);
}
__device__ __forceinline__ void cpasync16(u32 dst, const void* src) {
    asm volatile("cp.async.cg.shared.global [%0], [%1], 16;" :: "r"(dst), "l"(src));
}
__device__ __forceinline__ void cpcommit() { asm volatile("cp.async.commit_group;" ::: "memory"); }
__device__ __forceinline__ void cpwait0()  { asm volatile("cp.async.wait_group 0;" ::: "memory"); }
__device__ __forceinline__ void cpwait1()  { asm volatile("cp.async.wait_group 1;" ::: "memory"); }

// ---------------- split: fp32 -> fp16 (hi only) ----------------------------
__global__ void split_hi_kernel(const float4* __restrict__ s, __half* __restrict__ h,
                                int n4) {
    int i = blockIdx.x * blockDim.x + threadIdx.x;
    if (i >= n4) return;
    float4 v = s[i];
    ((u32*)h)[2 * i]     = packh(v.x, v.y);
    ((u32*)h)[2 * i + 1] = packh(v.z, v.w);
}

// ===========================================================================
// GEMM (NT): C = Ah Bh^T, pure fp16 HMMA; output fp32 or fp16 (template).
// 128x256 CTA tile, BK=64, 512 threads = 16 warps (4M x 4N), warp tile 32x64.
// ===========================================================================
#define GROW 144
#define GAST 18432
#define GBST 36864
#define GST1  (GAST + GBST)              // 55296
#define GEMM1T_SMEM (2 * GST1)           // 110592

__device__ __forceinline__ void stage_loads1(
    const __half* __restrict__ Ah, const __half* __restrict__ Bh,
    int K, int bm, int bn, int k0, u32 buf, int t) {
#pragma unroll
    for (int i = 0; i < 2; i++) {
        const int id = t + i * 512, row = id >> 3, cq = id & 7;
        const u32 d = buf + (u32)(row * GROW + cq * 16);
        cpasync16(d, Ah + (size_t)(bm + row) * K + k0 + cq * 8);
    }
#pragma unroll
    for (int i = 0; i < 4; i++) {
        const int id = t + i * 512, row = id >> 3, cq = id & 7;
        const u32 d = buf + GAST + (u32)(row * GROW + cq * 16);
        cpasync16(d, Bh + (size_t)(bn + row) * K + k0 + cq * 8);
    }
}

template <int HALF_OUT>
__global__ __launch_bounds__(512, 1)
void gemm_f16_1t(const __half* __restrict__ Ah, const __half* __restrict__ Bh,
                 void* __restrict__ Cv, int M, int N, int K) {
    extern __shared__ char smc[];
    const u32 sb = smem_u32(smc);

    const int t = threadIdx.x, lane = t & 31, w = t >> 5;
    const int g = lane >> 2, tq = lane & 3;
    const int wm = w & 3, wn = w >> 2;
    const int bm = blockIdx.y * 128, bn = blockIdx.x * 256;

    float acc[2][8][4];
#pragma unroll
    for (int mt = 0; mt < 2; mt++)
#pragma unroll
        for (int nt = 0; nt < 8; nt++)
#pragma unroll
            for (int i = 0; i < 4; i++) acc[mt][nt][i] = 0.0f;

    const int NS = K / 64;
    stage_loads1(Ah, Bh, K, bm, bn, 0, sb, t);
    cpcommit();

    const u32 arowl = (u32)(wm * 32 + (lane & 7) + ((lane >> 3) & 1) * 8);
    const u32 acoff = (u32)((lane >> 4) * 16);
    const u32 browl = (u32)(wn * 64 + (lane & 7) + ((lane >> 4) & 1) * 8);
    const u32 bcoff = (u32)(((lane >> 3) & 1) * 16);

    for (int s = 0; s < NS; s++) {
        if (s + 1 < NS) {
            stage_loads1(Ah, Bh, K, bm, bn, (s + 1) * 64,
                         sb + (u32)((s + 1) & 1) * GST1, t);
            cpcommit();
            cpwait1();
        } else {
            cpwait0();
        }
        __syncthreads();

        const u32 sbuf = sb + (u32)(s & 1) * GST1;
#pragma unroll
        for (int c = 0; c < 4; c++) {
            u32 ah[2][4], bh[8][2];
#pragma unroll
            for (int mt = 0; mt < 2; mt++)
                ldsm4(ah[mt], sbuf + (arowl + mt * 16) * GROW + c * 32 + acoff);
#pragma unroll
            for (int p = 0; p < 4; p++) {
                u32 r[4];
                ldsm4(r, sbuf + GAST + (browl + p * 16) * GROW + c * 32 + bcoff);
                bh[2 * p][0] = r[0]; bh[2 * p][1] = r[1];
                bh[2 * p + 1][0] = r[2]; bh[2 * p + 1][1] = r[3];
            }
#pragma unroll
            for (int nt = 0; nt < 8; nt++)
#pragma unroll
                for (int mt = 0; mt < 2; mt++)
                    mma16816(acc[mt][nt], ah[mt][0], ah[mt][1], ah[mt][2], ah[mt][3],
                             bh[nt][0], bh[nt][1]);
        }
        __syncthreads();
    }

#pragma unroll
    for (int mt = 0; mt < 2; mt++) {
        const int r0 = bm + wm * 32 + mt * 16 + g;
#pragma unroll
        for (int nt = 0; nt < 8; nt++) {
            const int cc = bn + wn * 64 + nt * 8 + 2 * tq;
            if (HALF_OUT) {
                __half* C = (__half*)Cv;
                *(u32*)&C[(size_t)r0 * N + cc]       = packh(acc[mt][nt][0], acc[mt][nt][1]);
                *(u32*)&C[(size_t)(r0 + 8) * N + cc] = packh(acc[mt][nt][2], acc[mt][nt][3]);
            } else {
                float* C = (float*)Cv;
                *(float2*)&C[(size_t)r0 * N + cc]       = make_float2(acc[mt][nt][0], acc[mt][nt][1]);
                *(float2*)&C[(size_t)(r0 + 8) * N + cc] = make_float2(acc[mt][nt][2], acc[mt][nt][3]);
            }
        }
    }
}

// ---------------- RoPE + GQA split (fp16 in, fp16 out) ---------------------
// Q pre-scaled by 0.125 * log2(e) so attention scores are in log2 domain.
#define QSCALE 0.180336880f   // 0.125 * 1.4426950408889634
__global__ void rope_split_kernel(const float* __restrict__ cosp,
                                  const float* __restrict__ sinp) {
    size_t idx = (size_t)blockIdx.x * blockDim.x + threadIdx.x;
    const size_t total = (size_t)B_ * T_ * QKV_F;
    if (idx >= total) return;

    const int d = (int)(idx & 63);
    const int f = (int)(idx % QKV_F);
    const size_t bt = idx / QKV_F;
    const int tpos = (int)(bt % T_);
    const int b = (int)(bt / T_);
    const int g = f / 384;
    const int slot = (f % 384) >> 6;

    float val = __half2float(g_qkv16[idx]);
    if (slot <= 4) {
        const int dh = d & 31;
        const float c = cosp[tpos * 32 + dh];
        const float s = sinp[tpos * 32 + dh];
        const float other = __half2float(g_qkv16[idx ^ 32]);
        val = (d < 32) ? (val * c - other * s) : fmaf(val, c, other * s);
    }

    if (slot < QPK_) {
        val *= QSCALE;   // fold 1/sqrt(D) * log2(e)
        const int h = g * QPK_ + slot;
        g_qh[(((size_t)b * H_ + h) * T_ + tpos) * D_ + d] = __float2half_rn(val);
    } else {
        const size_t o = (((size_t)b * G_ + g) * T_ + tpos) * D_ + d;
        if (slot == QPK_) g_kh[o] = __float2half_rn(val);
        else              g_vh[o] = __float2half_rn(val);
    }
}

// ===========================================================================
// Flash attention, pure fp16 HMMA: S (log2 domain) = Qh Kh^T, O += Ph Vh.
// Softmax: exp2f, lazy max-rescale (only when row max grows).
// Block (b,h,128 q rows), 256 threads = 8 warps, kv tile 64, 2-stage cp.async.
// ===========================================================================
#define AS  72
#define ASW 36
#define AQB   18432
#define AKVST 18432
#define AT_SMEM_BYTES (AQB + 2 * AKVST)     // 55296

__global__ __launch_bounds__(256, 2) void attn_mma_kernel() {
    extern __shared__ char smc[];
    const u32 sb = smem_u32(smc);
    __half* Qh = (__half*)smc;
    u32* QhW = (u32*)Qh;

    const int t = threadIdx.x, lane = t & 31, w = t >> 5;
    const int g = lane >> 2, tq = lane & 3;
    const int qt = blockIdx.x, h = blockIdx.y, b = blockIdx.z, grp = h >> 2;

    {   // stage Q (128 x 64)
        const __half* Qg = g_qh + (((size_t)b * H_ + h) * T_ + (size_t)qt * 128) * D_;
#pragma unroll
        for (int i = 0; i < 4; i++) {
            const int e = t + i * 256, row = e >> 3, c8 = (e & 7) * 8;
            *(uint4*)&Qh[row * AS + c8] = *(const uint4*)&Qg[row * D_ + c8];
        }
    }

    float oacc[8][4];
#pragma unroll
    for (int dt = 0; dt < 8; dt++)
#pragma unroll
        for (int i = 0; i < 4; i++) oacc[dt][i] = 0.0f;
    float mrow[2] = {-1e30f, -1e30f};
    float lrow[2] = {0.0f, 0.0f};

    const size_t kvbase = ((size_t)b * G_ + grp) * T_ * D_;
    const int NKT = T_ / 64;

    {   // prologue: stage kt=0
        const u32 base = sb + AQB;
#pragma unroll
        for (int i = 0; i < 2; i++) {
            const int id = t + i * 256, row = id >> 3, cq = id & 7;
            const u32 d = base + (u32)(row * 144 + cq * 16);
            const size_t go = kvbase + (size_t)row * 64 + cq * 8;
            cpasync16(d, g_kh + go); cpasync16(d + 9216, g_vh + go);
        }
        cpcommit();
    }

    for (int kt = 0; kt < NKT; kt++) {
        if (kt + 1 < NKT) {
            const size_t kb = kvbase + (size_t)(kt + 1) * 64 * D_;
            const u32 base = sb + AQB + (u32)((kt + 1) & 1) * AKVST;
#pragma unroll
            for (int i = 0; i < 2; i++) {
                const int id = t + i * 256, row = id >> 3, cq = id & 7;
                const u32 d = base + (u32)(row * 144 + cq * 16);
                const size_t go = kb + (size_t)row * 64 + cq * 8;
                cpasync16(d, g_kh + go); cpasync16(d + 9216, g_vh + go);
            }
            cpcommit();
            cpwait1();
        } else {
            cpwait0();
        }
        __syncthreads();

        const char* stb = smc + AQB + (size_t)(kt & 1) * AKVST;
        const u32* KhW = (const u32*)(stb);
        const __half* Vh = (const __half*)(stb + 9216);

        // ---- S (log2 units) = Qh Kh^T ----
        float sacc[8][4];
#pragma unroll
        for (int nt = 0; nt < 8; nt++)
#pragma unroll
            for (int i = 0; i < 4; i++) sacc[nt][i] = 0.0f;

        const int qw = (w * 16 + g) * ASW + tq;
#pragma unroll
        for (int c = 0; c < 4; c++) {
            const int qo = qw + c * 8;
            const u32 ah0 = QhW[qo],     ah1 = QhW[qo + 8 * ASW];
            const u32 ah2 = QhW[qo + 4], ah3 = QhW[qo + 8 * ASW + 4];
#pragma unroll
            for (int nt = 0; nt < 8; nt++) {
                const int ko = (nt * 8 + g) * ASW + tq + c * 8;
                mma16816(sacc[nt], ah0, ah1, ah2, ah3, KhW[ko], KhW[ko + 4]);
            }
        }

        // ---- online softmax (base-2, lazy rescale) ----
#pragma unroll
        for (int r = 0; r < 2; r++) {
            float rmax = -1e30f;
#pragma unroll
            for (int nt = 0; nt < 8; nt++)
                rmax = fmaxf(rmax, fmaxf(sacc[nt][2 * r], sacc[nt][2 * r + 1]));
            rmax = fmaxf(rmax, __shfl_xor_sync(0xffffffffu, rmax, 1));
            rmax = fmaxf(rmax, __shfl_xor_sync(0xffffffffu, rmax, 2));
            if (rmax > mrow[r]) {       // lazy rescale only on new max
                const float corr = exp2f(mrow[r] - rmax);
                lrow[r] *= corr;
#pragma unroll
                for (int dt = 0; dt < 8; dt++) {
                    oacc[dt][2 * r] *= corr; oacc[dt][2 * r + 1] *= corr;
                }
                mrow[r] = rmax;
            }
            const float mn = mrow[r];
            float rs = 0.0f;
#pragma unroll
            for (int nt = 0; nt < 8; nt++) {
                const float p0 = exp2f(sacc[nt][2 * r] - mn);
                const float p1 = exp2f(sacc[nt][2 * r + 1] - mn);
                sacc[nt][2 * r] = p0; sacc[nt][2 * r + 1] = p1;
                rs += p0 + p1;
            }
            rs += __shfl_xor_sync(0xffffffffu, rs, 1);
            rs += __shfl_xor_sync(0xffffffffu, rs, 2);
            lrow[r] += rs;
        }

        // ---- O += Ph Vh ----
        const int vrow = lane & 15;
        const int vcol = (lane >> 4) << 3;
#pragma unroll
        for (int c = 0; c < 4; c++) {
            u32 ph[4];
            ph[0] = packh(sacc[2 * c][0],     sacc[2 * c][1]);
            ph[1] = packh(sacc[2 * c][2],     sacc[2 * c][3]);
            ph[2] = packh(sacc[2 * c + 1][0], sacc[2 * c + 1][1]);
            ph[3] = packh(sacc[2 * c + 1][2], sacc[2 * c + 1][3]);
#pragma unroll
            for (int d2 = 0; d2 < 4; d2++) {
                u32 vh[4];
                ldsm4t(vh, &Vh[(c * 16 + vrow) * AS + d2 * 16 + vcol]);
                mma16816(oacc[2 * d2],     ph[0], ph[1], ph[2], ph[3], vh[0], vh[1]);
                mma16816(oacc[2 * d2 + 1], ph[0], ph[1], ph[2], ph[3], vh[2], vh[3]);
            }
        }
        __syncthreads();
    }

    // ---- normalize + write fp16 att ----
    const float inv0 = 1.0f / lrow[0];
    const float inv1 = 1.0f / lrow[1];
    const size_t row0 = (size_t)b * T_ + (size_t)qt * 128 + w * 16 + g;
    const size_t row1 = row0 + 8;
#pragma unroll
    for (int dt = 0; dt < 8; dt++) {
        const int col = h * D_ + dt * 8 + 2 * tq;
        *(u32*)&g_ath[row0 * E_ + col] = packh(oacc[dt][0] * inv0, oacc[dt][1] * inv0);
        *(u32*)&g_ath[row1 * E_ + col] = packh(oacc[dt][2] * inv1, oacc[dt][3] * inv1);
    }
}

// ---------------------------------------------------------------------------
extern "C" void kernel_launch(void* const* d_in, const int* in_sizes, int n_in,
                              void* d_out, int out_size) {
    const float *x = 0, *cosp = 0, *sinp = 0, *attn_w = 0, *proj_w = 0;
    for (int i = 0; i < n_in; i++) {
        const float* p = (const float*)d_in[i];
        switch (in_sizes[i]) {
            case 8388608: x = p; break;
            case 6291456: attn_w = p; break;
            case 4194304: proj_w = p; break;
            case 65536:   if (!cosp) cosp = p; else sinp = p; break;
            default: break;
        }
    }
    float* out = (float*)d_out;

    __half *qkv16, *xh, *awh, *pwh, *ath;
    cudaGetSymbolAddress((void**)&qkv16, g_qkv16);
    cudaGetSymbolAddress((void**)&xh,  g_xh);
    cudaGetSymbolAddress((void**)&awh, g_awh);
    cudaGetSymbolAddress((void**)&pwh, g_pwh);
    cudaGetSymbolAddress((void**)&ath, g_ath);

    // 0) fp32 -> fp16
    split_hi_kernel<<<(8388608 / 4 + 255) / 256, 256>>>((const float4*)x, xh, 8388608 / 4);
    split_hi_kernel<<<(6291456 / 4 + 255) / 256, 256>>>((const float4*)attn_w, awh, 6291456 / 4);
    split_hi_kernel<<<(4194304 / 4 + 255) / 256, 256>>>((const float4*)proj_w, pwh, 4194304 / 4);

    // 1) qkv = x @ attn_w^T  (fp16 out)
    cudaFuncSetAttribute((const void*)gemm_f16_1t<1>,
                         cudaFuncAttributeMaxDynamicSharedMemorySize, GEMM1T_SMEM);
    cudaFuncSetAttribute((const void*)gemm_f16_1t<0>,
                         cudaFuncAttributeMaxDynamicSharedMemorySize, GEMM1T_SMEM);
    gemm_f16_1t<1><<<dim3(QKV_F / 256, (B_ * T_) / 128), 512, GEMM1T_SMEM>>>(
        xh, awh, qkv16, B_ * T_, QKV_F, E_);

    // 2) RoPE + GQA split -> fp16 q/k/v (q in log2-softmax scale)
    const size_t total = (size_t)B_ * T_ * QKV_F;
    rope_split_kernel<<<(unsigned)((total + 255) / 256), 256>>>(cosp, sinp);

    // 3) attention
    cudaFuncSetAttribute((const void*)attn_mma_kernel,
                         cudaFuncAttributeMaxDynamicSharedMemorySize, AT_SMEM_BYTES);
    attn_mma_kernel<<<dim3(T_ / 128, H_, B_), 256, AT_SMEM_BYTES>>>();

    // 4) out = att @ proj_w^T  (fp32 out)
    gemm_f16_1t<0><<<dim3(E_ / 256, (B_ * T_) / 128), 512, GEMM1T_SMEM>>>(
        ath, pwh, out, B_ * T_, E_, E_);
}